// round 3
// baseline (speedup 1.0000x reference)
#include <cuda_runtime.h>
#include <math.h>

// Problem shapes (fixed by the dataset's setup_inputs)
#define BATCH   2
#define NMAPS   16
#define CH      256
#define HWPIX   4096   // 64*64
#define TDIM    1024
#define PIX     64     // pixels per block tile
#define NTHREADS 512
#define SMEM_BYTES (2 * CH * PIX * 4)   // two 64KB x-slab buffers

// Precomputed scaled query-key vector: qk[b][c] = scale * sum_o q[b,o]*Wk[o,c]
__device__ float g_qk[BATCH * CH];

// ---------------- cp.async helpers ----------------
__device__ __forceinline__ void cp16(float* dst_smem, const float* src) {
    unsigned d = (unsigned)__cvta_generic_to_shared(dst_smem);
    asm volatile("cp.async.cg.shared.global [%0], [%1], 16;" :: "r"(d), "l"(src));
}
__device__ __forceinline__ void cp_commit() { asm volatile("cp.async.commit_group;" ::: "memory"); }
__device__ __forceinline__ void cp_wait0()  { asm volatile("cp.async.wait_group 0;" ::: "memory"); }
__device__ __forceinline__ void cp_wait1()  { asm volatile("cp.async.wait_group 1;" ::: "memory"); }

// ---------------- Kernel 1: compute qk[b][:] (tiny) ----------------
// q[b,o] = sum_t tr[b,t]*Wq[o,t] + bq[o];  qk[b,c] = scale * sum_o q[b,o]*Wk[o,c]
__global__ void __launch_bounds__(256) prep_kernel(
    const float* __restrict__ tr, const float* __restrict__ Wq,
    const float* __restrict__ bq, const float* __restrict__ Wk)
{
    __shared__ float t_s[TDIM];
    __shared__ float q_s[CH];
    const int b   = blockIdx.x;
    const int tid = threadIdx.x;

    for (int i = tid; i < TDIM; i += 256) t_s[i] = tr[b * TDIM + i];
    __syncthreads();

    const int lane = tid & 31;
    const int wid  = tid >> 5;   // 8 warps
    for (int o = wid; o < CH; o += 8) {
        const float* wrow = Wq + (size_t)o * TDIM;
        float acc = 0.f;
        for (int j = lane; j < TDIM; j += 32) acc += wrow[j] * t_s[j];
        #pragma unroll
        for (int off = 16; off > 0; off >>= 1) acc += __shfl_xor_sync(0xffffffffu, acc, off);
        if (lane == 0) q_s[o] = acc + bq[o];
    }
    __syncthreads();

    // one thread per output channel c (256 threads)
    const float scale = rsqrtf((float)CH);   // C^-0.5 = 0.0625
    const int c = tid;
    float acc0 = 0.f, acc1 = 0.f;
    #pragma unroll 4
    for (int o = 0; o < CH; o += 2) {
        acc0 += q_s[o]     * Wk[(size_t)o * CH + c];
        acc1 += q_s[o + 1] * Wk[(size_t)(o + 1) * CH + c];
    }
    g_qk[b * CH + c] = (acc0 + acc1) * scale;
}

// ---------------- Kernel 2: fused scores + online softmax + weighted sum + Wv GEMM ----------------
// Block tile: one b, 64 contiguous pixels. Streams the 16 m-slabs [256c x 64px]
// through double-buffered smem (single DRAM read of residual_maps).
__global__ void __launch_bounds__(NTHREADS, 1) main_kernel(
    const float* __restrict__ xg, const float* __restrict__ Wv,
    const float* __restrict__ bv, float* __restrict__ out)
{
    extern __shared__ float smem[];          // 2 buffers of CH*PIX floats
    __shared__ float qk_s[CH];
    __shared__ float red[8][PIX];
    __shared__ __align__(16) float w_s[PIX];
    __shared__ __align__(16) float corr_s[PIX];
    __shared__ __align__(16) float rmax_s[PIX];
    __shared__ __align__(16) float rsum_s[PIX];

    const int tid  = threadIdx.x;
    const int b    = blockIdx.x / (HWPIX / PIX);
    const int pix0 = (blockIdx.x % (HWPIX / PIX)) * PIX;

    float* buf[2] = { smem, smem + CH * PIX };

    for (int i = tid; i < CH; i += NTHREADS) qk_s[i] = g_qk[b * CH + i];
    if (tid < PIX) { rmax_s[tid] = -1e30f; rsum_s[tid] = 0.f; }

    // y accumulator: thread owns channels cg*8..cg*8+7, pixel quad pq (pixels 4pq..4pq+3)
    const int cg = tid >> 4;   // 0..31
    const int pq = tid & 15;   // 0..15
    float4 yacc[8];
    #pragma unroll
    for (int i = 0; i < 8; i++) yacc[i] = make_float4(0.f, 0.f, 0.f, 0.f);

    const float* base = xg + (size_t)b * NMAPS * CH * HWPIX + pix0;

    // prologue: stage 0 -> buf0
    {
        const float* bm = base;
        #pragma unroll
        for (int k = 0; k < 8; k++) {
            int i4 = tid + k * NTHREADS;         // 0..4095
            int c  = i4 >> 4;
            int q  = i4 & 15;
            cp16(buf[0] + i4 * 4, bm + (size_t)c * HWPIX + 4 * q);
        }
        cp_commit();
    }

    for (int m = 0; m < NMAPS; m++) {
        float* bufc = buf[m & 1];
        // prefetch next slab
        if (m + 1 < NMAPS) {
            float* bufn = buf[(m + 1) & 1];
            const float* bm = base + (size_t)(m + 1) * CH * HWPIX;
            #pragma unroll
            for (int k = 0; k < 8; k++) {
                int i4 = tid + k * NTHREADS;
                int c  = i4 >> 4;
                int q  = i4 & 15;
                cp16(bufn + i4 * 4, bm + (size_t)c * HWPIX + 4 * q);
            }
            cp_commit();
            cp_wait1();
        } else {
            cp_wait0();
        }
        __syncthreads();

        // Phase A: partial score dot. thread (g = c-group of 32, p = pixel)
        {
            const int g = tid >> 6;      // 0..7
            const int p = tid & 63;      // 0..63
            const float* xc  = bufc + (size_t)(g * 32) * PIX + p;
            const float* qkc = qk_s + g * 32;
            float a0 = 0.f, a1 = 0.f, a2 = 0.f, a3 = 0.f;
            #pragma unroll
            for (int i = 0; i < 32; i += 4) {
                a0 += qkc[i    ] * xc[(i    ) * PIX];
                a1 += qkc[i + 1] * xc[(i + 1) * PIX];
                a2 += qkc[i + 2] * xc[(i + 2) * PIX];
                a3 += qkc[i + 3] * xc[(i + 3) * PIX];
            }
            red[g][p] = (a0 + a1) + (a2 + a3);
        }
        __syncthreads();

        // online softmax state update (one thread per pixel)
        if (tid < PIX) {
            float s = red[0][tid] + red[1][tid] + red[2][tid] + red[3][tid]
                    + red[4][tid] + red[5][tid] + red[6][tid] + red[7][tid];
            float om = rmax_s[tid];
            float nm = fmaxf(om, s);
            float cr = __expf(om - nm);
            float w  = __expf(s - nm);
            rsum_s[tid] = rsum_s[tid] * cr + w;
            rmax_s[tid] = nm;
            w_s[tid]    = w;
            corr_s[tid] = cr;
        }
        __syncthreads();

        // Phase B: y = y*corr + w*x  (conflict-free LDS.128)
        {
            const float4* x4 = (const float4*)bufc;
            float4 wv = *(const float4*)&w_s[4 * pq];
            float4 cv = *(const float4*)&corr_s[4 * pq];
            #pragma unroll
            for (int i = 0; i < 8; i++) {
                int c = cg * 8 + i;
                float4 xv = x4[c * 16 + pq];
                yacc[i].x = yacc[i].x * cv.x + wv.x * xv.x;
                yacc[i].y = yacc[i].y * cv.y + wv.y * xv.y;
                yacc[i].z = yacc[i].z * cv.z + wv.z * xv.z;
                yacc[i].w = yacc[i].w * cv.w + wv.w * xv.w;
            }
        }
        __syncthreads();   // protect bufc from next prefetch overwrite
    }

    // normalize y and stash into buf0 (free after last slab went to buf1)
    {
        float4 rs = *(const float4*)&rsum_s[4 * pq];
        float4 inv = make_float4(1.f / rs.x, 1.f / rs.y, 1.f / rs.z, 1.f / rs.w);
        float4* y4 = (float4*)buf[0];
        #pragma unroll
        for (int i = 0; i < 8; i++) {
            int c = cg * 8 + i;
            float4 v = make_float4(yacc[i].x * inv.x, yacc[i].y * inv.y,
                                   yacc[i].z * inv.z, yacc[i].w * inv.w);
            y4[c * 16 + pq] = v;
        }
    }
    __syncthreads();

    // Epilogue GEMM: out[o, p] = sum_c Wv[o,c] * y[c,p] + bv[o]
    // thread owns 8 output channels (og*8..+7) x 4 pixels (4pq..+3)
    {
        const int og = tid >> 4;   // 0..31
        float4 acc[8];
        #pragma unroll
        for (int i = 0; i < 8; i++) {
            float bvi = bv[og * 8 + i];
            acc[i] = make_float4(bvi, bvi, bvi, bvi);
        }
        const float4* Wv4 = (const float4*)Wv;
        const float4* y4  = (const float4*)buf[0];

        #pragma unroll 4
        for (int c4 = 0; c4 < CH / 4; c4++) {
            float4 y0 = y4[(4 * c4 + 0) * 16 + pq];
            float4 y1 = y4[(4 * c4 + 1) * 16 + pq];
            float4 y2 = y4[(4 * c4 + 2) * 16 + pq];
            float4 y3 = y4[(4 * c4 + 3) * 16 + pq];
            #pragma unroll
            for (int i = 0; i < 8; i++) {
                float4 wv = Wv4[(size_t)(og * 8 + i) * (CH / 4) + c4];
                acc[i].x += wv.x * y0.x + wv.y * y1.x + wv.z * y2.x + wv.w * y3.x;
                acc[i].y += wv.x * y0.y + wv.y * y1.y + wv.z * y2.y + wv.w * y3.y;
                acc[i].z += wv.x * y0.z + wv.y * y1.z + wv.z * y2.z + wv.w * y3.z;
                acc[i].w += wv.x * y0.w + wv.y * y1.w + wv.z * y2.w + wv.w * y3.w;
            }
        }
        #pragma unroll
        for (int i = 0; i < 8; i++) {
            int o = og * 8 + i;
            *(float4*)(out + ((size_t)b * CH + o) * HWPIX + pix0 + 4 * pq) = acc[i];
        }
    }
}

extern "C" void kernel_launch(void* const* d_in, const int* in_sizes, int n_in,
                              void* d_out, int out_size)
{
    const float* tr = (const float*)d_in[0];   // [B, T]
    const float* x  = (const float*)d_in[1];   // [B, M, C, H, W]
    const float* Wq = (const float*)d_in[2];   // [C, T]
    const float* bq = (const float*)d_in[3];   // [C]
    const float* Wk = (const float*)d_in[4];   // [C, C]
    // d_in[5] = bk: constant across softmax axis -> cancels, unused
    const float* Wv = (const float*)d_in[6];   // [C, C]
    const float* bv = (const float*)d_in[7];   // [C]
    float* out = (float*)d_out;                // [B, C, H, W]

    (void)in_sizes; (void)n_in; (void)out_size;

    cudaFuncSetAttribute(main_kernel, cudaFuncAttributeMaxDynamicSharedMemorySize, SMEM_BYTES);

    prep_kernel<<<BATCH, 256>>>(tr, Wq, bq, Wk);
    main_kernel<<<BATCH * (HWPIX / PIX), NTHREADS, SMEM_BYTES>>>(x, Wv, bv, out);
}

// round 4
// speedup vs baseline: 2.2230x; 2.2230x over previous
#include <cuda_runtime.h>
#include <math.h>

// Problem shapes (fixed by the dataset's setup_inputs)
#define BATCH   2
#define NMAPS   16
#define CH      256
#define HWPIX   4096   // 64*64
#define TDIM    1024
#define PIX     64     // pixels per block tile
#define NTHREADS 512
#define SMEM_BYTES (2 * CH * PIX * 4)   // two 64KB x-slab buffers

// Intermediates in device globals (no allocation allowed)
__device__ float g_q[BATCH * CH];    // q = tr @ Wq^T + bq
__device__ float g_qk[BATCH * CH];   // qk = scale * Wk^T q

// ---------------- cp.async helpers ----------------
__device__ __forceinline__ void cp16(float* dst_smem, const float* src) {
    unsigned d = (unsigned)__cvta_generic_to_shared(dst_smem);
    asm volatile("cp.async.cg.shared.global [%0], [%1], 16;" :: "r"(d), "l"(src));
}
__device__ __forceinline__ void cp_commit() { asm volatile("cp.async.commit_group;" ::: "memory"); }
__device__ __forceinline__ void cp_wait0()  { asm volatile("cp.async.wait_group 0;" ::: "memory"); }
__device__ __forceinline__ void cp_wait1()  { asm volatile("cp.async.wait_group 1;" ::: "memory"); }

// ---------------- Prep stage 1: q[b][o] = tr[b,:]·Wq[o,:] + bq[o] ----------------
// grid (32, B) x 256 threads, 8 warps/block, warp per output channel o.
__global__ void __launch_bounds__(256) prep1_kernel(
    const float* __restrict__ tr, const float* __restrict__ Wq,
    const float* __restrict__ bq)
{
    const int b    = blockIdx.y;
    const int lane = threadIdx.x & 31;
    const int wid  = threadIdx.x >> 5;
    const int o    = blockIdx.x * 8 + wid;

    const float* wrow = Wq + (size_t)o * TDIM;
    const float* trow = tr + (size_t)b * TDIM;
    float acc = 0.f;
    #pragma unroll 4
    for (int j = lane; j < TDIM; j += 32) acc += wrow[j] * trow[j];
    #pragma unroll
    for (int off = 16; off > 0; off >>= 1) acc += __shfl_xor_sync(0xffffffffu, acc, off);
    if (lane == 0) g_q[b * CH + o] = acc + bq[o];
}

// ---------------- Prep stage 2: qk[b][c] = scale * sum_o q[b,o]*Wk[o,c] ----------------
// grid (8, B) x 256 threads. Block handles 32 columns; 8 o-groups of 32.
__global__ void __launch_bounds__(256) prep2_kernel(const float* __restrict__ Wk)
{
    __shared__ float part[8][32];
    const int b  = blockIdx.y;
    const int c0 = blockIdx.x * 32;
    const int og = threadIdx.x >> 5;   // 0..7
    const int ci = threadIdx.x & 31;
    const int c  = c0 + ci;

    const float* qb = g_q + b * CH;
    float acc = 0.f;
    #pragma unroll 8
    for (int i = 0; i < 32; i++) {
        int o = og * 32 + i;
        acc += qb[o] * Wk[(size_t)o * CH + c];
    }
    part[og][ci] = acc;
    __syncthreads();
    if (threadIdx.x < 32) {
        float s = part[0][ci] + part[1][ci] + part[2][ci] + part[3][ci]
                + part[4][ci] + part[5][ci] + part[6][ci] + part[7][ci];
        g_qk[b * CH + c0 + ci] = s * 0.0625f;   // CH^-0.5
    }
}

// ---------------- Main kernel: fused scores + online softmax + weighted sum + Wv GEMM ----------------
__global__ void __launch_bounds__(NTHREADS, 1) main_kernel(
    const float* __restrict__ xg, const float* __restrict__ Wv,
    const float* __restrict__ bv, float* __restrict__ out)
{
    extern __shared__ float smem[];          // 2 buffers of CH*PIX floats
    __shared__ float qk_s[CH];
    __shared__ __align__(16) float red_s[NTHREADS * 4];   // per-thread float4 partial scores
    __shared__ __align__(16) float w_s[PIX];
    __shared__ __align__(16) float corr_s[PIX];
    __shared__ __align__(16) float rmax_s[PIX];
    __shared__ __align__(16) float rsum_s[PIX];

    const int tid  = threadIdx.x;
    const int b    = blockIdx.x / (HWPIX / PIX);
    const int pix0 = (blockIdx.x % (HWPIX / PIX)) * PIX;

    float* buf[2] = { smem, smem + CH * PIX };

    for (int i = tid; i < CH; i += NTHREADS) qk_s[i] = g_qk[b * CH + i];
    if (tid < PIX) { rmax_s[tid] = -1e30f; rsum_s[tid] = 0.f; }

    // Thread owns channels cg*8..cg*8+7 and pixel quad pq (pixels 4pq..4pq+3)
    const int cg = tid >> 4;   // 0..31
    const int pq = tid & 15;   // 0..15

    const float* base = xg + (size_t)b * NMAPS * CH * HWPIX + pix0;

    // prologue: stage slab 0 -> buf0
    {
        const float* bm = base;
        #pragma unroll
        for (int k = 0; k < 8; k++) {
            int i4 = tid + k * NTHREADS;
            int c  = i4 >> 4;
            int q  = i4 & 15;
            cp16(buf[0] + i4 * 4, bm + (size_t)c * HWPIX + 4 * q);
        }
        cp_commit();
    }
    __syncthreads();   // qk_s / softmax state visible

    // hoist qk values for this thread's channels into registers
    float qkr[8];
    #pragma unroll
    for (int i = 0; i < 8; i++) qkr[i] = qk_s[cg * 8 + i];

    float4 yacc[8];
    #pragma unroll
    for (int i = 0; i < 8; i++) yacc[i] = make_float4(0.f, 0.f, 0.f, 0.f);

    for (int m = 0; m < NMAPS; m++) {
        float* bufc = buf[m & 1];
        if (m + 1 < NMAPS) {
            float* bufn = buf[(m + 1) & 1];
            const float* bm = base + (size_t)(m + 1) * CH * HWPIX;
            #pragma unroll
            for (int k = 0; k < 8; k++) {
                int i4 = tid + k * NTHREADS;
                int c  = i4 >> 4;
                int q  = i4 & 15;
                cp16(bufn + i4 * 4, bm + (size_t)c * HWPIX + 4 * q);
            }
            cp_commit();
            cp_wait1();
        } else {
            cp_wait0();
        }
        __syncthreads();   // sync A: current buffer ready; red_s free for reuse

        // Phase A: load x into registers, compute partial scores for 4 pixels
        float4 xv[8];
        float4 ps = make_float4(0.f, 0.f, 0.f, 0.f);
        {
            const float4* x4 = (const float4*)bufc;
            #pragma unroll
            for (int i = 0; i < 8; i++) {
                int c = cg * 8 + i;
                xv[i] = x4[c * 16 + pq];
                ps.x += qkr[i] * xv[i].x;
                ps.y += qkr[i] * xv[i].y;
                ps.z += qkr[i] * xv[i].z;
                ps.w += qkr[i] * xv[i].w;
            }
            *(float4*)&red_s[(cg * 16 + pq) * 4] = ps;
        }
        __syncthreads();   // sync B: all bufc reads + red_s writes done

        // Reduce 32 cg-partials per pixel + online softmax (64 threads)
        if (tid < PIX) {
            float s = 0.f;
            #pragma unroll
            for (int g = 0; g < 32; g++) s += red_s[g * 64 + tid];
            float om = rmax_s[tid];
            float nm = fmaxf(om, s);
            float cr = __expf(om - nm);
            float w  = __expf(s - nm);
            rsum_s[tid] = rsum_s[tid] * cr + w;
            rmax_s[tid] = nm;
            w_s[tid]    = w;
            corr_s[tid] = cr;
        }
        __syncthreads();   // sync C: w/corr ready

        // Phase B: y = y*corr + w*x  — pure register work, no smem x re-read
        {
            float4 wv = *(const float4*)&w_s[4 * pq];
            float4 cv = *(const float4*)&corr_s[4 * pq];
            #pragma unroll
            for (int i = 0; i < 8; i++) {
                yacc[i].x = yacc[i].x * cv.x + wv.x * xv[i].x;
                yacc[i].y = yacc[i].y * cv.y + wv.y * xv[i].y;
                yacc[i].z = yacc[i].z * cv.z + wv.z * xv[i].z;
                yacc[i].w = yacc[i].w * cv.w + wv.w * xv[i].w;
            }
        }
        // no sync needed: next iteration's cp.async targets bufc, but every
        // thread's bufc reads happened before sync B of this iteration.
    }

    // normalize y and stash into buf0 (free: last slab lives in buf1)
    __syncthreads();
    {
        float4 rs = *(const float4*)&rsum_s[4 * pq];
        float4 inv = make_float4(1.f / rs.x, 1.f / rs.y, 1.f / rs.z, 1.f / rs.w);
        float4* y4 = (float4*)buf[0];
        #pragma unroll
        for (int i = 0; i < 8; i++) {
            int c = cg * 8 + i;
            y4[c * 16 + pq] = make_float4(yacc[i].x * inv.x, yacc[i].y * inv.y,
                                          yacc[i].z * inv.z, yacc[i].w * inv.w);
        }
    }
    __syncthreads();

    // Epilogue GEMM: out[o, p] = sum_c Wv[o,c] * y[c,p] + bv[o]
    {
        const int og = tid >> 4;   // 0..31
        float4 acc[8];
        #pragma unroll
        for (int i = 0; i < 8; i++) {
            float bvi = bv[og * 8 + i];
            acc[i] = make_float4(bvi, bvi, bvi, bvi);
        }
        const float4* Wv4 = (const float4*)Wv;
        const float4* y4  = (const float4*)buf[0];

        #pragma unroll 4
        for (int c4 = 0; c4 < CH / 4; c4++) {
            float4 y0 = y4[(4 * c4 + 0) * 16 + pq];
            float4 y1 = y4[(4 * c4 + 1) * 16 + pq];
            float4 y2 = y4[(4 * c4 + 2) * 16 + pq];
            float4 y3 = y4[(4 * c4 + 3) * 16 + pq];
            #pragma unroll
            for (int i = 0; i < 8; i++) {
                float4 wv = Wv4[(size_t)(og * 8 + i) * (CH / 4) + c4];
                acc[i].x += wv.x * y0.x + wv.y * y1.x + wv.z * y2.x + wv.w * y3.x;
                acc[i].y += wv.x * y0.y + wv.y * y1.y + wv.z * y2.y + wv.w * y3.y;
                acc[i].z += wv.x * y0.z + wv.y * y1.z + wv.z * y2.z + wv.w * y3.z;
                acc[i].w += wv.x * y0.w + wv.y * y1.w + wv.z * y2.w + wv.w * y3.w;
            }
        }
        #pragma unroll
        for (int i = 0; i < 8; i++) {
            int o = og * 8 + i;
            *(float4*)(out + ((size_t)b * CH + o) * HWPIX + pix0 + 4 * pq) = acc[i];
        }
    }
}

extern "C" void kernel_launch(void* const* d_in, const int* in_sizes, int n_in,
                              void* d_out, int out_size)
{
    const float* tr = (const float*)d_in[0];   // [B, T]
    const float* x  = (const float*)d_in[1];   // [B, M, C, H, W]
    const float* Wq = (const float*)d_in[2];   // [C, T]
    const float* bq = (const float*)d_in[3];   // [C]
    const float* Wk = (const float*)d_in[4];   // [C, C]
    // d_in[5] = bk: constant across the softmax axis -> cancels, unused
    const float* Wv = (const float*)d_in[6];   // [C, C]
    const float* bv = (const float*)d_in[7];   // [C]
    float* out = (float*)d_out;                // [B, C, H, W]

    (void)in_sizes; (void)n_in; (void)out_size;

    cudaFuncSetAttribute(main_kernel, cudaFuncAttributeMaxDynamicSharedMemorySize, SMEM_BYTES);

    prep1_kernel<<<dim3(32, BATCH), 256>>>(tr, Wq, bq);
    prep2_kernel<<<dim3(8, BATCH), 256>>>(Wk);
    main_kernel<<<BATCH * (HWPIX / PIX), NTHREADS, SMEM_BYTES>>>(x, Wv, bv, out);
}